// round 3
// baseline (speedup 1.0000x reference)
#include <cuda_runtime.h>
#include <cuda_bf16.h>

// SRU PROJ forward:
//   g1  = sigmoid(u1 + bias)
//   cur = (cur - u0) * g1 + u0
// u: [L, B, D, 2] f32, bias: [D], init: [B, D]
// out: c: [L, B, D] followed by last: [B, D] (if out_size includes it).
//
// One thread per (b, d) column; serial loop over L. Loads of u are
// independent of the recurrence, so unrolling gives MLP for latency hiding.
// All accesses are fully coalesced (adjacent d -> adjacent addresses).

__global__ __launch_bounds__(256, 1)
void sru_fwd_kernel(const float2* __restrict__ u,
                    const float*  __restrict__ bias,
                    const float*  __restrict__ init,
                    float*        __restrict__ c,
                    float*        __restrict__ last,
                    int L, int BD, int D)
{
    const int idx = blockIdx.x * blockDim.x + threadIdx.x;
    if (idx >= BD) return;

    const float bb  = __ldg(&bias[idx % D]);
    float cur = init[idx];

    const float2* up = u + idx;   // stride BD (float2 elements) per timestep
    float*        cp = c + idx;   // stride BD (floats) per timestep

    #pragma unroll 8
    for (int l = 0; l < L; ++l) {
        const float2 v = up[l * BD];
        // g = sigmoid(u1 + bias)
        const float g = __fdividef(1.0f, 1.0f + __expf(-(v.y + bb)));
        // cur = (cur - u0) * g + u0
        cur = fmaf(cur - v.x, g, v.x);
        cp[l * BD] = cur;
    }

    if (last) last[idx] = cur;
}

extern "C" void kernel_launch(void* const* d_in, const int* in_sizes, int n_in,
                              void* d_out, int out_size)
{
    const float2* u    = (const float2*)d_in[0];
    const float*  bias = (const float*) d_in[1];
    const float*  init = (const float*) d_in[2];

    const int D  = in_sizes[1];            // 1024
    const int BD = in_sizes[2];            // B * D = 32768
    const int L  = in_sizes[0] / (BD * 2); // 1024

    float* c = (float*)d_out;
    float* last = nullptr;
    const long long c_elems = (long long)L * (long long)BD;
    if ((long long)out_size >= c_elems + BD) {
        last = c + c_elems;   // last state appended after c
    }

    const int threads = 256;
    const int blocks  = (BD + threads - 1) / threads;
    sru_fwd_kernel<<<blocks, threads>>>(u, bias, init, c, last, L, BD, D);
}

// round 4
// speedup vs baseline: 1.6929x; 1.6929x over previous
#include <cuda_runtime.h>
#include <cuda_bf16.h>

// SRU PROJ forward:
//   g1  = sigmoid(u1 + bias)
//   cur = (cur - u0) * g1 + u0
// u: [L, B, D, 2] f32, bias: [D], init: [B, D]
// out: c: [L, B, D] (+ last: [B, D] appended if out_size allows).
//
// One thread per (b, d) column; serial over L. Explicit double-buffered
// software pipeline: prefetch next BATCH of float2 loads before computing
// the current batch, so ~16 loads/thread are in flight continuously
// (~28 KB/SM >= the ~25 KB needed to cover 577-cycle DRAM latency at the
// per-SM bandwidth share). Streaming hints since there is zero reuse.

#define SRU_BATCH 16

__global__ __launch_bounds__(256, 1)
void sru_fwd_kernel(const float2* __restrict__ u,
                    const float*  __restrict__ bias,
                    const float*  __restrict__ init,
                    float*        __restrict__ c,
                    float*        __restrict__ last,
                    int L, int BD, int D)
{
    const int idx = blockIdx.x * blockDim.x + threadIdx.x;
    if (idx >= BD) return;

    const float bb = __ldg(&bias[idx % D]);
    float cur = init[idx];

    const float2* up = u + idx;   // stride BD float2 per timestep
    float*        cp = c + idx;   // stride BD floats per timestep

    float2 bufA[SRU_BATCH];
    float2 bufB[SRU_BATCH];

    // Prologue: fill buffer A with batch 0.
    #pragma unroll
    for (int i = 0; i < SRU_BATCH; ++i)
        bufA[i] = __ldcs(&up[i * BD]);

    // Main loop: ping-pong, two batches per iteration so buffers stay in
    // registers with no copies.
    for (int base = 0; base < L; base += 2 * SRU_BATCH) {
        // Prefetch batch (base + BATCH) into B while computing A.
        const int nb1 = base + SRU_BATCH;
        if (nb1 < L) {
            #pragma unroll
            for (int i = 0; i < SRU_BATCH; ++i)
                bufB[i] = __ldcs(&up[(nb1 + i) * BD]);
        }
        #pragma unroll
        for (int i = 0; i < SRU_BATCH; ++i) {
            const float2 v = bufA[i];
            const float g = __fdividef(1.0f, 1.0f + __expf(-(v.y + bb)));
            cur = fmaf(cur - v.x, g, v.x);
            __stcs(&cp[(base + i) * BD], cur);
        }

        // Prefetch batch (base + 2*BATCH) into A while computing B.
        const int nb2 = base + 2 * SRU_BATCH;
        if (nb2 < L) {
            #pragma unroll
            for (int i = 0; i < SRU_BATCH; ++i)
                bufA[i] = __ldcs(&up[(nb2 + i) * BD]);
        }
        if (nb1 < L) {
            #pragma unroll
            for (int i = 0; i < SRU_BATCH; ++i) {
                const float2 v = bufB[i];
                const float g = __fdividef(1.0f, 1.0f + __expf(-(v.y + bb)));
                cur = fmaf(cur - v.x, g, v.x);
                __stcs(&cp[(nb1 + i) * BD], cur);
            }
        }
    }

    if (last) last[idx] = cur;
}

extern "C" void kernel_launch(void* const* d_in, const int* in_sizes, int n_in,
                              void* d_out, int out_size)
{
    const float2* u    = (const float2*)d_in[0];
    const float*  bias = (const float*) d_in[1];
    const float*  init = (const float*) d_in[2];

    const int D  = in_sizes[1];            // 1024
    const int BD = in_sizes[2];            // B * D = 32768
    const int L  = in_sizes[0] / (BD * 2); // 1024

    float* c = (float*)d_out;
    float* last = nullptr;
    const long long c_elems = (long long)L * (long long)BD;
    if ((long long)out_size >= c_elems + BD) {
        last = c + c_elems;
    }

    const int threads = 256;
    const int blocks  = (BD + threads - 1) / threads;
    sru_fwd_kernel<<<blocks, threads>>>(u, bias, init, c, last, L, BD, D);
}

// round 5
// speedup vs baseline: 1.7244x; 1.0186x over previous
#include <cuda_runtime.h>
#include <cuda_bf16.h>

// SRU PROJ forward:
//   g1  = sigmoid(u1 + bias)
//   cur = (cur - u0) * g1 + u0
// u: [L, B, D, 2] f32, bias: [D], init: [B, D]
// out: c: [L, B, D] (+ last: [B, D] appended if out_size allows).
//
// One thread per (b, d) column; serial over L. Double-buffered register
// pipeline (BATCH=16 float2 in flight per thread) to cover DRAM latency.
// R4 change: 64-thread blocks, 512 blocks -> all 148 SMs active (the 128x256
// launch left 20 SMs idle; chip is DRAM-request-parallelism bound, so idle
// SMs cost linearly).

#define SRU_BATCH 16

__global__ __launch_bounds__(64, 4)
void sru_fwd_kernel(const float2* __restrict__ u,
                    const float*  __restrict__ bias,
                    const float*  __restrict__ init,
                    float*        __restrict__ c,
                    float*        __restrict__ last,
                    int L, int BD, int D)
{
    const int idx = blockIdx.x * blockDim.x + threadIdx.x;
    if (idx >= BD) return;

    const float bb = __ldg(&bias[idx % D]);
    float cur = init[idx];

    const float2* up = u + idx;   // stride BD float2 per timestep
    float*        cp = c + idx;   // stride BD floats per timestep

    float2 bufA[SRU_BATCH];
    float2 bufB[SRU_BATCH];

    // Prologue: fill buffer A with batch 0.
    #pragma unroll
    for (int i = 0; i < SRU_BATCH; ++i)
        bufA[i] = __ldcs(&up[i * BD]);

    // Main loop: ping-pong, two batches per iteration so buffers stay in
    // registers with no copies.
    for (int base = 0; base < L; base += 2 * SRU_BATCH) {
        // Prefetch batch (base + BATCH) into B while computing A.
        const int nb1 = base + SRU_BATCH;
        if (nb1 < L) {
            #pragma unroll
            for (int i = 0; i < SRU_BATCH; ++i)
                bufB[i] = __ldcs(&up[(nb1 + i) * BD]);
        }
        #pragma unroll
        for (int i = 0; i < SRU_BATCH; ++i) {
            const float2 v = bufA[i];
            const float g = __fdividef(1.0f, 1.0f + __expf(-(v.y + bb)));
            cur = fmaf(cur - v.x, g, v.x);
            __stcs(&cp[(base + i) * BD], cur);
        }

        // Prefetch batch (base + 2*BATCH) into A while computing B.
        const int nb2 = base + 2 * SRU_BATCH;
        if (nb2 < L) {
            #pragma unroll
            for (int i = 0; i < SRU_BATCH; ++i)
                bufA[i] = __ldcs(&up[(nb2 + i) * BD]);
        }
        if (nb1 < L) {
            #pragma unroll
            for (int i = 0; i < SRU_BATCH; ++i) {
                const float2 v = bufB[i];
                const float g = __fdividef(1.0f, 1.0f + __expf(-(v.y + bb)));
                cur = fmaf(cur - v.x, g, v.x);
                __stcs(&cp[(nb1 + i) * BD], cur);
            }
        }
    }

    if (last) last[idx] = cur;
}

extern "C" void kernel_launch(void* const* d_in, const int* in_sizes, int n_in,
                              void* d_out, int out_size)
{
    const float2* u    = (const float2*)d_in[0];
    const float*  bias = (const float*) d_in[1];
    const float*  init = (const float*) d_in[2];

    const int D  = in_sizes[1];            // 1024
    const int BD = in_sizes[2];            // B * D = 32768
    const int L  = in_sizes[0] / (BD * 2); // 1024

    float* c = (float*)d_out;
    float* last = nullptr;
    const long long c_elems = (long long)L * (long long)BD;
    if ((long long)out_size >= c_elems + BD) {
        last = c + c_elems;
    }

    const int threads = 64;
    const int blocks  = (BD + threads - 1) / threads;   // 512
    sru_fwd_kernel<<<blocks, threads>>>(u, bias, init, c, last, L, BD, D);
}